// round 11
// baseline (speedup 1.0000x reference)
#include <cuda_runtime.h>
#include <cuda_bf16.h>
#include <stdint.h>
#include <math.h>

#define BATCH 4096
#define NROWS 8192
#define DIM   128
#define INV_T 2.0f            // 1 / 0.5
#define NTILE 64              // 8192 / 128

#define BM 128
#define BN 128
#define NTHR 256

#define PADF 136              // floats per smem tile row (bank-stagger 8)
#define PAD2 68               // float2 per row
#define ROWB (PADF * 4)       // 544 bytes
#define TILE_SMEM (BM * ROWB) // 69632 bytes per tile buffer
#define RED_OFF   (3 * TILE_SMEM)
#define SMEM_TOTAL (RED_OFF + 1536 * 4)   // + red[512] + redc[1024]

#define E2 7.3890560989306495f

typedef unsigned long long ull;

// ---------------- device scratch (allocation-free) ----------------
__device__ __align__(16) float g_zt[NROWS * DIM];  // tf32-rounded, (k,k+4)-interleaved
__device__ float g_pos[BATCH];
__device__ float g_denom[NROWS];

// ---------------- helpers ----------------
__device__ __forceinline__ uint32_t sptr(const void* p) {
    uint32_t a;
    asm("{ .reg .u64 t; cvta.to.shared.u64 t, %1; cvt.u32.u64 %0, t; }"
        : "=r"(a) : "l"(p));
    return a;
}
__device__ __forceinline__ uint32_t to_tf32(float f) {
    uint32_t r;
    asm("cvt.rna.tf32.f32 %0, %1;" : "=r"(r) : "f"(f));
    return r;
}
__device__ __forceinline__ ull pack2(float lo, float hi) {
    ull r;
    asm("mov.b64 %0, {%1, %2};" : "=l"(r) : "f"(lo), "f"(hi));
    return r;
}
__device__ __forceinline__ void unpack2(ull v, float &lo, float &hi) {
    asm("mov.b64 {%0, %1}, %2;" : "=f"(lo), "=f"(hi) : "l"(v));
}
__device__ __forceinline__ ull fma2n(ull a, ull b, ull c) {
    ull d;
    asm("fma.rn.f32x2 %0, %1, %2, %3;" : "=l"(d) : "l"(a), "l"(b), "l"(c));
    return d;
}
__device__ __forceinline__ ull mul2(ull a, ull b) {
    ull d;
    asm("mul.rn.f32x2 %0, %1, %2;" : "=l"(d) : "l"(a), "l"(b));
    return d;
}
__device__ __forceinline__ ull add2(ull a, ull b) {
    ull d;
    asm("add.rn.f32x2 %0, %1, %2;" : "=l"(d) : "l"(a), "l"(b));
    return d;
}

// mma.sync m16n8k8 tf32: c += a * b
__device__ __forceinline__ void mma_tf32(float* c, float2 ag, float2 ag8, float2 b) {
    uint32_t a0 = __float_as_uint(ag.x),  a1 = __float_as_uint(ag8.x);
    uint32_t a2 = __float_as_uint(ag.y),  a3 = __float_as_uint(ag8.y);
    uint32_t b0 = __float_as_uint(b.x),   b1 = __float_as_uint(b.y);
    asm volatile(
        "mma.sync.aligned.m16n8k8.row.col.f32.tf32.tf32.f32 "
        "{%0,%1,%2,%3}, {%4,%5,%6,%7}, {%8,%9}, {%0,%1,%2,%3};"
        : "+f"(c[0]), "+f"(c[1]), "+f"(c[2]), "+f"(c[3])
        : "r"(a0), "r"(a1), "r"(a2), "r"(a3), "r"(b0), "r"(b1));
}

#define CP_ASYNC16(dst_u32, src_ptr) \
    asm volatile("cp.async.cg.shared.global [%0], [%1], 16;" \
                 :: "r"(dst_u32), "l"(src_ptr) : "memory")
#define CP_COMMIT() asm volatile("cp.async.commit_group;" ::: "memory")
#define CP_WAIT1()  asm volatile("cp.async.wait_group 1;" ::: "memory")
#define CP_WAIT0()  asm volatile("cp.async.wait_group 0;" ::: "memory")

// stage a 128x128 float tile (pair-interleaved layout preserved) into padded smem
__device__ __forceinline__ void stage_tile(char* dst, const float* src, int tid) {
    #pragma unroll
    for (int i = tid; i < 4096; i += NTHR) {      // 4096 16B chunks
        int row = i >> 5;
        int cs  = i & 31;
        uint32_t d = sptr(dst + row * ROWB + cs * 16);
        const char* s = (const char*)(src + (size_t)row * DIM) + cs * 16;
        CP_ASYNC16(d, s);
    }
}

// packed exp(2s): degree-6 Taylor on y=s/2, then two squarings
__device__ __forceinline__ ull exp2s_p(ull s) {
    const ull C720 = pack2(1.38888888889e-3f, 1.38888888889e-3f);
    const ull C120 = pack2(8.33333333333e-3f, 8.33333333333e-3f);
    const ull C24  = pack2(4.16666666667e-2f, 4.16666666667e-2f);
    const ull C6   = pack2(1.66666666667e-1f, 1.66666666667e-1f);
    const ull CH   = pack2(0.5f, 0.5f);
    const ull C1   = pack2(1.0f, 1.0f);
    ull y = mul2(s, CH);
    ull p = fma2n(C720, y, C120);
    p = fma2n(p, y, C24);
    p = fma2n(p, y, C6);
    p = fma2n(p, y, CH);
    p = fma2n(p, y, C1);
    p = fma2n(p, y, C1);     // ~= exp(y)
    p = mul2(p, p);          // exp(s)
    return mul2(p, p);       // exp(2s)
}

// ---------------- k_norm: normalize + tf32 store + fused positives + denom init ----------------
__global__ void k_norm(const float* __restrict__ ei, const float* __restrict__ ej) {
    int w    = (blockIdx.x * blockDim.x + threadIdx.x) >> 5;
    int lane = threadIdx.x & 31;
    if (w >= NROWS) return;
    if (lane == 0) g_denom[w] = 0.0f;     // fused init

    const float* src = (w < BATCH) ? (ei + (size_t)w * DIM)
                                   : (ej + (size_t)(w - BATCH) * DIM);
    float4 v = ((const float4*)src)[lane];
    float ss = v.x*v.x + v.y*v.y + v.z*v.z + v.w*v.w;

    if (w < BATCH) {
        float4 u = ((const float4*)(ej + (size_t)w * DIM))[lane];
        float s2 = u.x*u.x + u.y*u.y + u.z*u.z + u.w*u.w;
        float dt = v.x*u.x + v.y*u.y + v.z*u.z + v.w*u.w;
        #pragma unroll
        for (int o = 16; o; o >>= 1) {
            ss += __shfl_xor_sync(0xffffffffu, ss, o);
            s2 += __shfl_xor_sync(0xffffffffu, s2, o);
            dt += __shfl_xor_sync(0xffffffffu, dt, o);
        }
        if (lane == 0)
            g_pos[w] = dt / (fmaxf(sqrtf(ss), 1e-12f) * fmaxf(sqrtf(s2), 1e-12f));
    } else {
        #pragma unroll
        for (int o = 16; o; o >>= 1) ss += __shfl_xor_sync(0xffffffffu, ss, o);
    }

    float s = 1.0f / fmaxf(sqrtf(ss), 1e-12f);
    float vv[4] = { v.x * s, v.y * s, v.z * s, v.w * s };
    // tf32-round + (k, k+4) pair-interleave: k = 8b+p -> slot = 8b + (p&3)*2 + (p>>2)
    #pragma unroll
    for (int c = 0; c < 4; ++c) {
        int k = lane * 4 + c;
        int b = k >> 3, p = k & 7;
        int slot = b * 8 + (p & 3) * 2 + (p >> 2);
        g_zt[(size_t)w * DIM + slot] = __uint_as_float(to_tf32(vv[c]));
    }
}

// ---------------- main: symmetric multi-tile GEMM, resident A, double-buffered B ----------------
// grid (64, 9): cgroup<8 -> 4 tiles by=4c..4c+3 (diag at c==0,t==0);
// cgroup==8 -> single tile by=32 (only bi<32).
__global__ void __launch_bounds__(NTHR, 1) k_main() {
    const int bi     = blockIdx.x;
    const int cgroup = blockIdx.y;
    if (cgroup == 8 && bi >= 32) return;
    const int nt = (cgroup == 8) ? 1 : 4;

    extern __shared__ char smem[];
    char* AsB    = smem;
    char* BsB[2] = { smem + TILE_SMEM, smem + 2 * TILE_SMEM };
    float* red   = (float*)(smem + RED_OFF);        // [128][4]
    float* redc  = red + 512;                       // [4*128][2]

    const int tid  = threadIdx.x;
    const int wid  = tid >> 5;
    const int lane = tid & 31;
    const int g    = lane >> 2;         // 0..7
    const int q    = lane & 3;          // 0..3
    const int wm   = wid >> 2;          // 0..1  (M warp, 64 rows)
    const int wn   = wid & 3;           // 0..3  (N warp, 32 cols)
    const int rowStart = bi * BM;

    // column tile index for step t
    #define BJ(t) ((cgroup < 8) ? ((bi + 4 * cgroup + (t)) & (NTILE - 1)) \
                                : ((bi + 32) & (NTILE - 1)))

    // prologue: A + B0 as group0; B1 as group1
    stage_tile(AsB,    g_zt + (size_t)rowStart * DIM, tid);
    stage_tile(BsB[0], g_zt + (size_t)BJ(0) * BM * DIM, tid);
    CP_COMMIT();
    if (nt > 1) {
        stage_tile(BsB[1], g_zt + (size_t)BJ(1) * BM * DIM, tid);
        CP_COMMIT();
        CP_WAIT1();
    } else {
        CP_WAIT0();
    }
    __syncthreads();

    const float2* As2 = (const float2*)AsB;

    float C[4][4][4];
    #pragma unroll
    for (int i = 0; i < 4; i++)
        #pragma unroll
        for (int j = 0; j < 4; j++)
            #pragma unroll
            for (int e = 0; e < 4; e++) C[i][j][e] = 0.0f;

    ull rs2[4][2];                // row sums, packed (lo=even cols, hi=odd)
    ull cs2[4][4];                // col sums per tile t, per j
    #pragma unroll
    for (int i = 0; i < 4; i++) { rs2[i][0] = 0ULL; rs2[i][1] = 0ULL; }
    #pragma unroll
    for (int t = 0; t < 4; t++)
        #pragma unroll
        for (int j = 0; j < 4; j++) cs2[t][j] = 0ULL;

    #pragma unroll
    for (int t = 0; t < 4; ++t) {
        if (t >= nt) break;
        if (t >= 1) {
            if (t + 1 < nt) {     // prefetch B[t+1] into buffer consumed at t-1
                stage_tile(BsB[(t + 1) & 1], g_zt + (size_t)BJ(t + 1) * BM * DIM, tid);
                CP_COMMIT();
                CP_WAIT1();
            } else {
                CP_WAIT0();
            }
            __syncthreads();
        }

        const float2* Bs2 = (const float2*)BsB[t & 1];

        #pragma unroll
        for (int ks = 0; ks < 16; ++ks) {
            float2 a0[4], a1[4], bb[4];
            #pragma unroll
            for (int i = 0; i < 4; i++) {
                int r0 = wm * 64 + i * 16 + g;
                a0[i] = As2[r0 * PAD2 + ks * 4 + q];
                a1[i] = As2[(r0 + 8) * PAD2 + ks * 4 + q];
            }
            #pragma unroll
            for (int j = 0; j < 4; j++) {
                int n0 = wn * 32 + j * 8 + g;
                bb[j] = Bs2[n0 * PAD2 + ks * 4 + q];
            }
            #pragma unroll
            for (int i = 0; i < 4; i++)
                #pragma unroll
                for (int j = 0; j < 4; j++)
                    mma_tf32(C[i][j], a0[i], a1[i], bb[j]);
        }

        // packed exp epilogue: accumulate row sums (registers, cross-tile) + col sums
        #pragma unroll
        for (int i = 0; i < 4; i++) {
            #pragma unroll
            for (int j = 0; j < 4; j++) {
                ull p0 = exp2s_p(pack2(C[i][j][0], C[i][j][1]));   // row half 0
                rs2[i][0] = add2(rs2[i][0], p0);
                cs2[t][j] = add2(cs2[t][j], p0);
                ull p1 = exp2s_p(pack2(C[i][j][2], C[i][j][3]));   // row half 1
                rs2[i][1] = add2(rs2[i][1], p1);
                cs2[t][j] = add2(cs2[t][j], p1);
                C[i][j][0] = 0.0f; C[i][j][1] = 0.0f;
                C[i][j][2] = 0.0f; C[i][j][3] = 0.0f;
            }
        }

        __syncthreads();   // protect B buffer for next prefetch
    }

    // ---- row-sum reduction (over q within quad, then over wn via smem) ----
    #pragma unroll
    for (int i = 0; i < 4; i++) {
        #pragma unroll
        for (int h = 0; h < 2; h++) {
            float lo, hi;
            unpack2(rs2[i][h], lo, hi);
            float v = lo + hi;
            v += __shfl_xor_sync(0xffffffffu, v, 1);
            v += __shfl_xor_sync(0xffffffffu, v, 2);
            if (q == 0) {
                int row = wm * 64 + i * 16 + h * 8 + g;
                red[row * 4 + wn] = v;
            }
        }
    }
    // ---- col-sum reduction (over g within warp, then over wm via smem) ----
    #pragma unroll
    for (int t = 0; t < 4; ++t) {
        if (t >= nt) break;
        const bool dskip = (cgroup == 0 && t == 0);
        if (!dskip) {
            #pragma unroll
            for (int j = 0; j < 4; j++) {
                float lo, hi;
                unpack2(cs2[t][j], lo, hi);
                #pragma unroll
                for (int o = 4; o <= 16; o <<= 1) {
                    lo += __shfl_xor_sync(0xffffffffu, lo, o);
                    hi += __shfl_xor_sync(0xffffffffu, hi, o);
                }
                if (g == 0) {
                    int col = wn * 32 + j * 8 + q * 2;
                    redc[(t * 128 + col) * 2 + wm]     = lo;
                    redc[(t * 128 + col + 1) * 2 + wm] = hi;
                }
            }
        }
    }
    __syncthreads();

    if (tid < BM) {
        float s = red[tid * 4] + red[tid * 4 + 1] + red[tid * 4 + 2] + red[tid * 4 + 3];
        if (cgroup == 0) s -= E2;   // remove diagonal exp(2*sim_rr) ~ e^2
        atomicAdd(&g_denom[rowStart + tid], s);
    }
    for (int idx = tid; idx < nt * 128; idx += NTHR) {
        int t = idx >> 7, col = idx & 127;
        if (!(cgroup == 0 && t == 0)) {
            float v = redc[idx * 2] + redc[idx * 2 + 1];
            atomicAdd(&g_denom[BJ(t) * BM + col], v);
        }
    }
    #undef BJ
}

// ---------------- final loss reduction ----------------
__global__ void k_loss(float* __restrict__ out) {
    int tid = threadIdx.x;
    float s = 0.0f;
    for (int r = tid; r < NROWS; r += 1024) {
        float p = g_pos[(r < BATCH) ? r : (r - BATCH)];
        s += logf(g_denom[r]) - p * INV_T;
    }
    __shared__ float red[1024];
    red[tid] = s;
    __syncthreads();
    #pragma unroll
    for (int st = 512; st; st >>= 1) {
        if (tid < st) red[tid] += red[tid + st];
        __syncthreads();
    }
    if (tid == 0) out[0] = red[0] / (float)NROWS;
}

extern "C" void kernel_launch(void* const* d_in, const int* in_sizes, int n_in,
                              void* d_out, int out_size) {
    const float* emb_i = (const float*)d_in[0];
    const float* emb_j = (const float*)d_in[1];
    float* out = (float*)d_out;
    (void)in_sizes; (void)n_in; (void)out_size;

    cudaFuncSetAttribute(k_main, cudaFuncAttributeMaxDynamicSharedMemorySize,
                         SMEM_TOTAL);

    k_norm<<<NROWS / 8, 256>>>(emb_i, emb_j);
    dim3 grid(NTILE, 9);
    k_main<<<grid, NTHR, SMEM_TOTAL>>>();
    k_loss<<<1, 1024>>>(out);
}

// round 12
// speedup vs baseline: 1.3759x; 1.3759x over previous
#include <cuda_runtime.h>
#include <cuda_bf16.h>
#include <stdint.h>
#include <math.h>

#define BATCH 4096
#define NROWS 8192
#define DIM   128
#define INV_T 2.0f            // 1 / 0.5
#define NTILE 64              // 8192 / 128

#define BM 128
#define NTHR 256

#define PADF 136              // floats per smem tile row (bank-stagger 8)
#define PAD2 68               // float2 per row
#define ROWB (PADF * 4)       // 544 bytes
#define TILE_SMEM (BM * ROWB) // 69632 bytes per 128-row tile buffer
#define SMEM_TOTAL (3 * TILE_SMEM)   // A(128 rows) + B(256 rows) = 208896

#define E2 7.3890560989306495f

// ---------------- device scratch (allocation-free) ----------------
__device__ __align__(16) float g_zt[NROWS * DIM];  // tf32-rounded, (k,k+4)-interleaved
__device__ float g_pos[BATCH];
__device__ float g_denom[NROWS];

// ---------------- helpers ----------------
__device__ __forceinline__ uint32_t sptr(const void* p) {
    uint32_t a;
    asm("{ .reg .u64 t; cvta.to.shared.u64 t, %1; cvt.u32.u64 %0, t; }"
        : "=r"(a) : "l"(p));
    return a;
}
__device__ __forceinline__ uint32_t to_tf32(float f) {
    uint32_t r;
    asm("cvt.rna.tf32.f32 %0, %1;" : "=r"(r) : "f"(f));
    return r;
}

// mma.sync m16n8k8 tf32: c += a * b
__device__ __forceinline__ void mma_tf32(float* c, float2 ag, float2 ag8, float2 b) {
    uint32_t a0 = __float_as_uint(ag.x),  a1 = __float_as_uint(ag8.x);
    uint32_t a2 = __float_as_uint(ag.y),  a3 = __float_as_uint(ag8.y);
    uint32_t b0 = __float_as_uint(b.x),   b1 = __float_as_uint(b.y);
    asm volatile(
        "mma.sync.aligned.m16n8k8.row.col.f32.tf32.tf32.f32 "
        "{%0,%1,%2,%3}, {%4,%5,%6,%7}, {%8,%9}, {%0,%1,%2,%3};"
        : "+f"(c[0]), "+f"(c[1]), "+f"(c[2]), "+f"(c[3])
        : "r"(a0), "r"(a1), "r"(a2), "r"(a3), "r"(b0), "r"(b1));
}

#define CP_ASYNC16(dst_u32, src_ptr) \
    asm volatile("cp.async.cg.shared.global [%0], [%1], 16;" \
                 :: "r"(dst_u32), "l"(src_ptr) : "memory")
#define CP_COMMIT() asm volatile("cp.async.commit_group;" ::: "memory")

// stage the kq-th K-quarter (8 16B-chunks per row) of a 128-row tile
__device__ __forceinline__ void stage_q(char* dst, const float* src, int tid, int kq) {
    #pragma unroll
    for (int i = tid; i < 1024; i += NTHR) {      // 1024 chunk jobs
        int row = i >> 3;
        int cc  = (i & 7) + kq * 8;
        uint32_t d = sptr(dst + row * ROWB + cc * 16);
        const char* s = (const char*)(src + (size_t)row * DIM) + cc * 16;
        CP_ASYNC16(d, s);
    }
}

// exp(2s): degree-6 Taylor on y=s/2, then two squarings (|s|<=1 -> rel err ~1e-6)
__device__ __forceinline__ float exp2s(float s) {
    float y = s * 0.5f;
    float p = fmaf(y, 1.38888888889e-3f, 8.33333333333e-3f);
    p = fmaf(p, y, 4.16666666667e-2f);
    p = fmaf(p, y, 1.66666666667e-1f);
    p = fmaf(p, y, 0.5f);
    p = fmaf(p, y, 1.0f);
    p = fmaf(p, y, 1.0f);     // ~= exp(y)
    p = p * p;                // exp(s)
    return p * p;             // exp(2s)
}

// ---------------- k_norm: normalize + tf32 store + fused positives + denom init ----------------
__global__ void k_norm(const float* __restrict__ ei, const float* __restrict__ ej) {
    int w    = (blockIdx.x * blockDim.x + threadIdx.x) >> 5;
    int lane = threadIdx.x & 31;
    if (w >= NROWS) return;
    if (lane == 0) g_denom[w] = 0.0f;     // fused init

    const float* src = (w < BATCH) ? (ei + (size_t)w * DIM)
                                   : (ej + (size_t)(w - BATCH) * DIM);
    float4 v = ((const float4*)src)[lane];
    float ss = v.x*v.x + v.y*v.y + v.z*v.z + v.w*v.w;

    if (w < BATCH) {
        float4 u = ((const float4*)(ej + (size_t)w * DIM))[lane];
        float s2 = u.x*u.x + u.y*u.y + u.z*u.z + u.w*u.w;
        float dt = v.x*u.x + v.y*u.y + v.z*u.z + v.w*u.w;
        #pragma unroll
        for (int o = 16; o; o >>= 1) {
            ss += __shfl_xor_sync(0xffffffffu, ss, o);
            s2 += __shfl_xor_sync(0xffffffffu, s2, o);
            dt += __shfl_xor_sync(0xffffffffu, dt, o);
        }
        if (lane == 0)
            g_pos[w] = dt / (fmaxf(sqrtf(ss), 1e-12f) * fmaxf(sqrtf(s2), 1e-12f));
    } else {
        #pragma unroll
        for (int o = 16; o; o >>= 1) ss += __shfl_xor_sync(0xffffffffu, ss, o);
    }

    float s = 1.0f / fmaxf(sqrtf(ss), 1e-12f);
    float vv[4] = { v.x * s, v.y * s, v.z * s, v.w * s };
    // tf32-round + (k, k+4) pair-interleave: k = 8b+p -> slot = 8b + (p&3)*2 + (p>>2)
    #pragma unroll
    for (int c = 0; c < 4; ++c) {
        int k = lane * 4 + c;
        int b = k >> 3, p = k & 7;
        int slot = b * 8 + (p & 3) * 2 + (p >> 2);
        g_zt[(size_t)w * DIM + slot] = __uint_as_float(to_tf32(vv[c]));
    }
}

// ---------------- main: symmetric 128x256 GEMM blocks + fused exp ----------------
// grid (64, 17): cy==0 -> diagonal tile (bi,bi) [first 128 cols valid];
// cy=1..16 -> col tiles bj1=(bi+2cy-1)&63, bj2=(bi+2cy)&63.
// Second tile invalid when cy==16 && bi>=32 (by=32 counted once).
__global__ void __launch_bounds__(NTHR, 1) k_main() {
    const int bi = blockIdx.x;
    const int cy = blockIdx.y;
    const bool diag   = (cy == 0);
    const int  bj1    = diag ? bi : (bi + 2 * cy - 1) & (NTILE - 1);
    const int  bj2    = (bi + 2 * cy) & (NTILE - 1);
    const bool valid2 = (cy >= 1) && (cy < 16 || bi < 32);

    extern __shared__ char smem[];
    char* As = smem;
    char* Bs = smem + TILE_SMEM;          // 256 rows (2 x 128-row tiles)

    const int tid  = threadIdx.x;
    const int wid  = tid >> 5;
    const int lane = tid & 31;
    const int g    = lane >> 2;         // 0..7
    const int q    = lane & 3;          // 0..3
    const int wm   = wid >> 2;          // 0..1  (M warp, 64 rows)
    const int wn   = wid & 3;           // 0..3  (N warp, 64 cols)
    const int rowStart = bi * BM;

    const float* srcA  = g_zt + (size_t)rowStart * DIM;
    const float* srcB1 = g_zt + (size_t)bj1 * BM * DIM;
    const float* srcB2 = g_zt + (size_t)bj2 * BM * DIM;

    // issue all 4 K-quarter stages (A + both B tiles per group)
    #pragma unroll
    for (int kq = 0; kq < 4; ++kq) {
        stage_q(As,             srcA,  tid, kq);
        stage_q(Bs,             srcB1, tid, kq);
        stage_q(Bs + TILE_SMEM, srcB2, tid, kq);
        CP_COMMIT();
    }

    const float2* As2 = (const float2*)As;
    const float2* Bs2 = (const float2*)Bs;

    float C[4][8][4];
    #pragma unroll
    for (int i = 0; i < 4; i++)
        #pragma unroll
        for (int j = 0; j < 8; j++)
            #pragma unroll
            for (int e = 0; e < 4; e++) C[i][j][e] = 0.0f;

    #pragma unroll
    for (int kq = 0; kq < 4; ++kq) {
        if (kq == 0)      asm volatile("cp.async.wait_group 3;" ::: "memory");
        else if (kq == 1) asm volatile("cp.async.wait_group 2;" ::: "memory");
        else if (kq == 2) asm volatile("cp.async.wait_group 1;" ::: "memory");
        else              asm volatile("cp.async.wait_group 0;" ::: "memory");
        __syncthreads();

        #pragma unroll
        for (int ki = 0; ki < 4; ++ki) {
            const int ks = kq * 4 + ki;
            float2 a0[4], a1[4], bb[8];
            #pragma unroll
            for (int i = 0; i < 4; i++) {
                int r0 = wm * 64 + i * 16 + g;
                a0[i] = As2[r0 * PAD2 + ks * 4 + q];
                a1[i] = As2[(r0 + 8) * PAD2 + ks * 4 + q];
            }
            #pragma unroll
            for (int j = 0; j < 8; j++) {
                int n0 = wn * 64 + j * 8 + g;
                bb[j] = Bs2[n0 * PAD2 + ks * 4 + q];
            }
            #pragma unroll
            for (int i = 0; i < 4; i++)
                #pragma unroll
                for (int j = 0; j < 8; j++)
                    mma_tf32(C[i][j], a0[i], a1[i], bb[j]);
        }
    }

    // epilogue: warps wn<2 own cols 0..127 (tile 1, always valid);
    // wn>=2 own cols 128..255 (tile 2, valid iff valid2)
    const bool contrib = (wn < 2) || valid2;

    float rs[4][2];      // [i][row parity]
    float cs[16];        // [j*2 + col parity]
    #pragma unroll
    for (int i = 0; i < 4; i++) { rs[i][0] = 0.0f; rs[i][1] = 0.0f; }
    #pragma unroll
    for (int e = 0; e < 16; e++) cs[e] = 0.0f;

    if (contrib) {
        #pragma unroll
        for (int i = 0; i < 4; i++)
            #pragma unroll
            for (int j = 0; j < 8; j++)
                #pragma unroll
                for (int r = 0; r < 4; r++) {
                    float ev = exp2s(C[i][j][r]);
                    rs[i][r >> 1] += ev;
                    cs[j * 2 + (r & 1)] += ev;
                }
    }

    __syncthreads();   // all mma reads done; overlay reductions on smem
    float* red  = (float*)smem;        // [128][4]
    float* redc = (float*)smem + 512;  // [256][2]

    // row sums: reduce over q within quad, stash per wn
    #pragma unroll
    for (int i = 0; i < 4; i++) {
        #pragma unroll
        for (int h = 0; h < 2; h++) {
            float v = rs[i][h];
            v += __shfl_xor_sync(0xffffffffu, v, 1);
            v += __shfl_xor_sync(0xffffffffu, v, 2);
            if (q == 0) {
                int row = wm * 64 + i * 16 + h * 8 + g;
                red[row * 4 + wn] = v;
            }
        }
    }
    // col sums: reduce over g within warp, stash per wm
    #pragma unroll
    for (int e = 0; e < 16; e++) {
        float v = cs[e];
        v += __shfl_xor_sync(0xffffffffu, v, 4);
        v += __shfl_xor_sync(0xffffffffu, v, 8);
        v += __shfl_xor_sync(0xffffffffu, v, 16);
        if (g == 0) {
            int col = wn * 64 + (e >> 1) * 8 + q * 2 + (e & 1);
            redc[col * 2 + wm] = v;
        }
    }
    __syncthreads();

    if (tid < BM) {
        float s = red[tid * 4] + red[tid * 4 + 1] + red[tid * 4 + 2] + red[tid * 4 + 3];
        if (diag) s -= E2;   // remove diagonal exp(2*sim_rr) ~ e^2
        atomicAdd(&g_denom[rowStart + tid], s);
    }
    // col scatter: tile 1 (skip for diag — rows already cover it), tile 2 if valid
    {
        float v = redc[tid * 2] + redc[tid * 2 + 1];
        if (tid < 128) {
            if (!diag) atomicAdd(&g_denom[bj1 * BM + tid], v);
        } else {
            if (valid2) atomicAdd(&g_denom[bj2 * BM + (tid - 128)], v);
        }
    }
}

// ---------------- final loss reduction ----------------
__global__ void k_loss(float* __restrict__ out) {
    int tid = threadIdx.x;
    float s = 0.0f;
    for (int r = tid; r < NROWS; r += 1024) {
        float p = g_pos[(r < BATCH) ? r : (r - BATCH)];
        s += logf(g_denom[r]) - p * INV_T;
    }
    __shared__ float red[1024];
    red[tid] = s;
    __syncthreads();
    #pragma unroll
    for (int st = 512; st; st >>= 1) {
        if (tid < st) red[tid] += red[tid + st];
        __syncthreads();
    }
    if (tid == 0) out[0] = red[0] / (float)NROWS;
}

extern "C" void kernel_launch(void* const* d_in, const int* in_sizes, int n_in,
                              void* d_out, int out_size) {
    const float* emb_i = (const float*)d_in[0];
    const float* emb_j = (const float*)d_in[1];
    float* out = (float*)d_out;
    (void)in_sizes; (void)n_in; (void)out_size;

    cudaFuncSetAttribute(k_main, cudaFuncAttributeMaxDynamicSharedMemorySize,
                         SMEM_TOTAL);

    k_norm<<<NROWS / 8, 256>>>(emb_i, emb_j);
    dim3 grid(NTILE, 17);
    k_main<<<grid, NTHR, SMEM_TOTAL>>>();
    k_loss<<<1, 1024>>>(out);
}

// round 13
// speedup vs baseline: 2.4881x; 1.8083x over previous
#include <cuda_runtime.h>
#include <cuda_fp16.h>
#include <stdint.h>
#include <math.h>

#define BATCH 4096
#define NROWS 8192
#define DIM   128
#define INV_T 2.0f            // 1 / 0.5
#define NTILE 64              // 8192 / 128

#define BM 128
#define BN 128
#define NTHR 256

#define ROWB 288              // 256B fp16 row data + 32B pad (bank-stagger 8)
#define ROW8 36               // ROWB / 8 (ull units)
#define TILE_SMEM (BM * ROWB) // 36864 bytes per tile buffer
#define SMEM_TOTAL (2 * TILE_SMEM)   // 73728 -> 2 CTAs/SM

#define E2 7.3890560989306495f

typedef unsigned long long ull;

// ---------------- device scratch (allocation-free) ----------------
// fp16 normalized rows; within each 16-k group, slot order
// [k0 k1 k8 k9 | k2 k3 k10 k11 | k4 k5 k12 k13 | k6 k7 k14 k15]
__device__ __align__(16) __half g_zh[NROWS * DIM];
__device__ float g_pos[BATCH];
__device__ float g_denom[NROWS];

// ---------------- helpers ----------------
__device__ __forceinline__ uint32_t sptr(const void* p) {
    uint32_t a;
    asm("{ .reg .u64 t; cvta.to.shared.u64 t, %1; cvt.u32.u64 %0, t; }"
        : "=r"(a) : "l"(p));
    return a;
}
__device__ __forceinline__ uint32_t lo32(ull v) { return (uint32_t)v; }
__device__ __forceinline__ uint32_t hi32(ull v) { return (uint32_t)(v >> 32); }

// mma.sync m16n8k16 fp16 -> fp32: c += a * b
__device__ __forceinline__ void mma_f16(float* c, uint32_t a0, uint32_t a1,
                                        uint32_t a2, uint32_t a3,
                                        uint32_t b0, uint32_t b1) {
    asm volatile(
        "mma.sync.aligned.m16n8k16.row.col.f32.f16.f16.f32 "
        "{%0,%1,%2,%3}, {%4,%5,%6,%7}, {%8,%9}, {%0,%1,%2,%3};"
        : "+f"(c[0]), "+f"(c[1]), "+f"(c[2]), "+f"(c[3])
        : "r"(a0), "r"(a1), "r"(a2), "r"(a3), "r"(b0), "r"(b1));
}

#define CP_ASYNC16(dst_u32, src_ptr) \
    asm volatile("cp.async.cg.shared.global [%0], [%1], 16;" \
                 :: "r"(dst_u32), "l"(src_ptr) : "memory")
#define CP_COMMIT() asm volatile("cp.async.commit_group;" ::: "memory")
#define CP_WAIT1()  asm volatile("cp.async.wait_group 1;" ::: "memory")
#define CP_WAIT0()  asm volatile("cp.async.wait_group 0;" ::: "memory")

// stage one K-half (8 of 16 16B-chunks per row) of a 128-row fp16 tile
__device__ __forceinline__ void stage_half(char* dst, const __half* src,
                                           int tid, int half) {
    #pragma unroll
    for (int i = tid; i < 1024; i += NTHR) {
        int row = i >> 3;
        int cc  = (i & 7) + half * 8;
        uint32_t d = sptr(dst + row * ROWB + cc * 16);
        const char* s = (const char*)(src + (size_t)row * DIM) + cc * 16;
        CP_ASYNC16(d, s);
    }
}

// exp(2s): degree-6 Taylor on y=s/2, then two squarings (|s|<=1 -> rel err ~1e-6)
__device__ __forceinline__ float exp2s(float s) {
    float y = s * 0.5f;
    float p = fmaf(y, 1.38888888889e-3f, 8.33333333333e-3f);
    p = fmaf(p, y, 4.16666666667e-2f);
    p = fmaf(p, y, 1.66666666667e-1f);
    p = fmaf(p, y, 0.5f);
    p = fmaf(p, y, 1.0f);
    p = fmaf(p, y, 1.0f);     // ~= exp(y)
    p = p * p;                // exp(s)
    return p * p;             // exp(2s)
}

// ---------------- k_norm: normalize + fp16 store + fused positives + denom init ----------------
__global__ void k_norm(const float* __restrict__ ei, const float* __restrict__ ej) {
    int w    = (blockIdx.x * blockDim.x + threadIdx.x) >> 5;
    int lane = threadIdx.x & 31;
    if (w >= NROWS) return;
    if (lane == 0) g_denom[w] = 0.0f;     // fused init

    const float* src = (w < BATCH) ? (ei + (size_t)w * DIM)
                                   : (ej + (size_t)(w - BATCH) * DIM);
    float4 v = ((const float4*)src)[lane];
    float ss = v.x*v.x + v.y*v.y + v.z*v.z + v.w*v.w;

    if (w < BATCH) {
        float4 u = ((const float4*)(ej + (size_t)w * DIM))[lane];
        float s2 = u.x*u.x + u.y*u.y + u.z*u.z + u.w*u.w;
        float dt = v.x*u.x + v.y*u.y + v.z*u.z + v.w*u.w;
        #pragma unroll
        for (int o = 16; o; o >>= 1) {
            ss += __shfl_xor_sync(0xffffffffu, ss, o);
            s2 += __shfl_xor_sync(0xffffffffu, s2, o);
            dt += __shfl_xor_sync(0xffffffffu, dt, o);
        }
        if (lane == 0)
            g_pos[w] = dt / (fmaxf(sqrtf(ss), 1e-12f) * fmaxf(sqrtf(s2), 1e-12f));
    } else {
        #pragma unroll
        for (int o = 16; o; o >>= 1) ss += __shfl_xor_sync(0xffffffffu, ss, o);
    }

    float s = 1.0f / fmaxf(sqrtf(ss), 1e-12f);
    float vv[4] = { v.x * s, v.y * s, v.z * s, v.w * s };

    // slot permutation: k = 16*K16 + p, pp=p>>1, P=p&1
    //   slot = 16*K16 + (pp&3)*4 + ((pp>>2)<<1) + P
    // thread handles k = 4*lane .. 4*lane+3 -> two adjacent-slot half2 stores
    __half* dstrow = g_zh + (size_t)w * DIM;
    {
        int k = 4 * lane;                 // pair (k, k+1)
        int K16 = k >> 4, pp = (k & 15) >> 1;
        int slot = K16 * 16 + (pp & 3) * 4 + ((pp >> 2) << 1);
        *(__half2*)(dstrow + slot) = __floats2half2_rn(vv[0], vv[1]);
    }
    {
        int k = 4 * lane + 2;             // pair (k+2, k+3)
        int K16 = k >> 4, pp = (k & 15) >> 1;
        int slot = K16 * 16 + (pp & 3) * 4 + ((pp >> 2) << 1);
        *(__half2*)(dstrow + slot) = __floats2half2_rn(vv[2], vv[3]);
    }
}

// ---------------- main: symmetric (upper-triangle) fp16 GEMM + fused exp ----------------
// grid (64, 33): by==0 -> diagonal tile (bi,bi); by 1..32 -> pair {bi, (bi+by)&63}
// (by==32 valid only for bi<32). Row sums -> denom[bi rows]; col sums -> denom[bj rows].
__global__ void __launch_bounds__(NTHR, 2) k_main() {
    const int bi = blockIdx.x;
    const int by = blockIdx.y;
    if (by == 32 && bi >= 32) return;
    const int bj    = (bi + by) & (NTILE - 1);
    const bool diag = (by == 0);

    extern __shared__ char smem[];
    char* As = smem;
    char* Bs = smem + TILE_SMEM;

    const int tid  = threadIdx.x;
    const int wid  = tid >> 5;
    const int lane = tid & 31;
    const int g    = lane >> 2;         // 0..7
    const int q    = lane & 3;          // 0..3
    const int wm   = wid >> 2;          // 0..1  (M warp, 64 rows)
    const int wn   = wid & 3;           // 0..3  (N warp, 32 cols)
    const int rowStart = bi * BM;
    const int colStart = bj * BN;

    const __half* srcA = g_zh + (size_t)rowStart * DIM;
    const __half* srcB = g_zh + (size_t)colStart * DIM;

    // stage both tiles, split by K-half for load/compute overlap
    stage_half(As, srcA, tid, 0);
    stage_half(Bs, srcB, tid, 0);
    CP_COMMIT();
    stage_half(As, srcA, tid, 1);
    stage_half(Bs, srcB, tid, 1);
    CP_COMMIT();

    const ull* As8 = (const ull*)As;
    const ull* Bs8 = (const ull*)Bs;

    float C[4][4][4];
    #pragma unroll
    for (int i = 0; i < 4; i++)
        #pragma unroll
        for (int j = 0; j < 4; j++)
            #pragma unroll
            for (int e = 0; e < 4; e++) C[i][j][e] = 0.0f;

    CP_WAIT1();
    __syncthreads();

    #pragma unroll
    for (int kh = 0; kh < 2; ++kh) {
        if (kh == 1) { CP_WAIT0(); __syncthreads(); }
        #pragma unroll
        for (int ki = 0; ki < 4; ++ki) {
            const int ks = kh * 4 + ki;          // K16-step 0..7
            ull alo[4], ahi[4], bv[4];
            #pragma unroll
            for (int i = 0; i < 4; i++) {
                int r0 = wm * 64 + i * 16 + g;
                alo[i] = As8[r0 * ROW8 + ks * 4 + q];
                ahi[i] = As8[(r0 + 8) * ROW8 + ks * 4 + q];
            }
            #pragma unroll
            for (int j = 0; j < 4; j++) {
                int n0 = wn * 32 + j * 8 + g;
                bv[j] = Bs8[n0 * ROW8 + ks * 4 + q];
            }
            #pragma unroll
            for (int i = 0; i < 4; i++)
                #pragma unroll
                for (int j = 0; j < 4; j++)
                    mma_f16(C[i][j],
                            lo32(alo[i]), lo32(ahi[i]),
                            hi32(alo[i]), hi32(ahi[i]),
                            lo32(bv[j]),  hi32(bv[j]));
        }
    }

    // epilogue: exp(2*sim); row sums (always) + col sums (off-diag)
    float rs[4][2];                 // [i][rowhalf]
    float cs[8];                    // [j*2 + colparity]
    #pragma unroll
    for (int i = 0; i < 4; i++) { rs[i][0] = 0.0f; rs[i][1] = 0.0f; }
    #pragma unroll
    for (int e = 0; e < 8; e++) cs[e] = 0.0f;

    #pragma unroll
    for (int i = 0; i < 4; i++)
        #pragma unroll
        for (int j = 0; j < 4; j++)
            #pragma unroll
            for (int r = 0; r < 4; r++) {
                float ev = exp2s(C[i][j][r]);
                rs[i][r >> 1] += ev;
                cs[j * 2 + (r & 1)] += ev;
            }

    __syncthreads();   // all mma reads of As/Bs done; reuse smem for reductions
    float* red  = (float*)smem;            // [128][4] row partials per wn
    float* redc = (float*)smem + 512;      // [128][2] col partials per wm

    // row sums: reduce over q (cols within quad)
    #pragma unroll
    for (int i = 0; i < 4; i++) {
        #pragma unroll
        for (int h = 0; h < 2; h++) {
            float v = rs[i][h];
            v += __shfl_xor_sync(0xffffffffu, v, 1);
            v += __shfl_xor_sync(0xffffffffu, v, 2);
            if (q == 0) {
                int row = wm * 64 + i * 16 + h * 8 + g;
                red[row * 4 + wn] = v;
            }
        }
    }
    // col sums: reduce over g (rows within warp)
    if (!diag) {
        #pragma unroll
        for (int e = 0; e < 8; e++) {
            float v = cs[e];
            v += __shfl_xor_sync(0xffffffffu, v, 4);
            v += __shfl_xor_sync(0xffffffffu, v, 8);
            v += __shfl_xor_sync(0xffffffffu, v, 16);
            if (g == 0) {
                int col = wn * 32 + (e >> 1) * 8 + q * 2 + (e & 1);
                redc[col * 2 + wm] = v;
            }
        }
    }
    __syncthreads();

    if (tid < BM) {
        float s = red[tid * 4] + red[tid * 4 + 1] + red[tid * 4 + 2] + red[tid * 4 + 3];
        if (diag) s -= E2;   // remove diagonal exp(2*sim_rr) ~ e^2
        atomicAdd(&g_denom[rowStart + tid], s);
        if (!diag) {
            float c = redc[tid * 2] + redc[tid * 2 + 1];
            atomicAdd(&g_denom[colStart + tid], c);
        }
    }
}

// ---------------- final loss reduction ----------------
__global__ void k_loss(float* __restrict__ out) {
    int tid = threadIdx.x;
    float s = 0.0f;
    for (int r = tid; r < NROWS; r += 1024) {
        float p = g_pos[(r < BATCH) ? r : (r - BATCH)];
        s += logf(g_denom[r]) - p * INV_T;
    }
    __shared__ float red[1024];
    red[tid] = s;
    __syncthreads();
    #pragma unroll
    for (int st = 512; st; st >>= 1) {
        if (tid < st) red[tid] += red[tid + st];
        __syncthreads();
    }
    if (tid == 0) out[0] = red[0] / (float)NROWS;
}

extern "C" void kernel_launch(void* const* d_in, const int* in_sizes, int n_in,
                              void* d_out, int out_size) {
    const float* emb_i = (const float*)d_in[0];
    const float* emb_j = (const float*)d_in[1];
    float* out = (float*)d_out;
    (void)in_sizes; (void)n_in; (void)out_size;

    cudaFuncSetAttribute(k_main, cudaFuncAttributeMaxDynamicSharedMemorySize,
                         SMEM_TOTAL);

    k_norm<<<NROWS / 8, 256>>>(emb_i, emb_j);
    dim3 grid(NTILE, 33);
    k_main<<<grid, NTHR, SMEM_TOTAL>>>();
    k_loss<<<1, 1024>>>(out);
}